// round 12
// baseline (speedup 1.0000x reference)
#include <cuda_runtime.h>
#include <cstdint>

// out[b,u] = prod_f(in[b,f]*w[f,u]) + bias[u] = P[b]*W[u] + bias[u]
// B=32768, F=32, U=256.
static constexpr int Bn = 32768;
static constexpr int Fn = 32;
static constexpr int Un = 256;

static constexpr int TILE_ROWS  = 32;            // 32 rows * 256 cols * 4B = 32 KB tile
static constexpr int TILE_BYTES = TILE_ROWS * Un * 4;
static constexpr int GRID       = Bn / TILE_ROWS; // 1024 blocks
static constexpr int THREADS    = 256;            // 8 warps * 4 rows = 32 rows

__device__ __forceinline__ uint32_t smem_u32(const void* p) {
    uint32_t a;
    asm("{ .reg .u64 t; cvta.to.shared.u64 t, %1; cvt.u32.u64 %0, t; }"
        : "=r"(a) : "l"(p));
    return a;
}

// Per block:
//   1. W[u] = prod_f w[f,u] into smem (one-time, 256 threads, coalesced)
//   2. each warp: 1 coalesced float4 input load (4 rows), shfl-reduce products
//   3. results written to a 32 KB smem tile via STS.128 (conflict-free)
//   4. fence.proxy.async + ONE cp.async.bulk (TMA bulk store) moves the whole
//      tile SMEM -> GMEM, bypassing the per-lane STG store path entirely.
__global__ __launch_bounds__(THREADS)
void fused_tma_kernel(const float* __restrict__ in,
                      const float* __restrict__ w,
                      const float* __restrict__ bias,
                      float* __restrict__ out) {
    __shared__ __align__(128) float tile[TILE_ROWS * Un];   // 32 KB
    __shared__ float sW[Un];

    const int t    = threadIdx.x;
    const int lane = t & 31;
    const int warp = t >> 5;                                // 0..7

    // ---- (2) issue the input load FIRST (overlaps W phase) ----
    const long long rowbase = (long long)blockIdx.x * TILE_ROWS + warp * 4;
    const float4* in4 = reinterpret_cast<const float4*>(in + rowbase * Fn);
    const float4 v = in4[lane];   // 4 rows * 32 f = 32 float4; lane l -> row l>>3

    // ---- (1) column products: thread t owns column t ----
    {
        float p0 = 1.0f, p1 = 1.0f, p2 = 1.0f, p3 = 1.0f;
#pragma unroll
        for (int f = 0; f < Fn; f += 4) {
            p0 *= w[(f + 0) * Un + t];
            p1 *= w[(f + 1) * Un + t];
            p2 *= w[(f + 2) * Un + t];
            p3 *= w[(f + 3) * Un + t];
        }
        sW[t] = (p0 * p1) * (p2 * p3);
    }

    // bias -> regs (independent; overlaps everything above)
    const float4* B4 = reinterpret_cast<const float4*>(bias);
    const float4 bv0 = B4[lane];
    const float4 bv1 = B4[lane + 32];

    __syncthreads();

    // W -> regs (lane owns float4 columns `lane` and `lane+32`)
    const float4* sW4 = reinterpret_cast<const float4*>(sW);
    const float4 wv0 = sW4[lane];
    const float4 wv1 = sW4[lane + 32];

    // row products within 8-lane groups
    float p = v.x * v.y * v.z * v.w;
    p *= __shfl_xor_sync(0xffffffffu, p, 1);
    p *= __shfl_xor_sync(0xffffffffu, p, 2);
    p *= __shfl_xor_sync(0xffffffffu, p, 4);
    // lanes 8r..8r+7 hold product of row (rowbase + r)

    // ---- (3) epilogue into smem tile (STS.128, conflict-free) ----
    float4* tile4 = reinterpret_cast<float4*>(tile) + (warp * 4) * (Un / 4);
#pragma unroll
    for (int r = 0; r < 4; ++r) {
        const float pr = __shfl_sync(0xffffffffu, p, r * 8);
        float4 o0, o1;
        o0.x = fmaf(pr, wv0.x, bv0.x);
        o0.y = fmaf(pr, wv0.y, bv0.y);
        o0.z = fmaf(pr, wv0.z, bv0.z);
        o0.w = fmaf(pr, wv0.w, bv0.w);
        o1.x = fmaf(pr, wv1.x, bv1.x);
        o1.y = fmaf(pr, wv1.y, bv1.y);
        o1.z = fmaf(pr, wv1.z, bv1.z);
        o1.w = fmaf(pr, wv1.w, bv1.w);
        tile4[r * 64 + lane]      = o0;   // 512B/warp contiguous: conflict-free
        tile4[r * 64 + lane + 32] = o1;
    }

    // make generic-proxy smem writes visible to the async (TMA) proxy
    asm volatile("fence.proxy.async.shared::cta;" ::: "memory");
    __syncthreads();

    // ---- (4) one bulk store for the whole 32 KB tile ----
    if (t == 0) {
        float* gdst = out + (long long)blockIdx.x * TILE_ROWS * Un;
        asm volatile(
            "cp.async.bulk.global.shared::cta.bulk_group [%0], [%1], %2;"
            :: "l"(gdst), "r"(smem_u32(tile)), "r"(TILE_BYTES)
            : "memory");
        asm volatile("cp.async.bulk.commit_group;" ::: "memory");
        asm volatile("cp.async.bulk.wait_group 0;" ::: "memory");
    }
}

extern "C" void kernel_launch(void* const* d_in, const int* in_sizes, int n_in,
                              void* d_out, int out_size) {
    // metadata order: inputs [B,F], weight [F,U], weight_selector [F,U] (dead), bias [U]
    const float* in   = (const float*)d_in[0];
    const float* w    = (const float*)d_in[1];
    const float* bias = (const float*)d_in[3];
    float* out        = (float*)d_out;

    fused_tma_kernel<<<GRID, THREADS>>>(in, w, bias, out);
}

// round 13
// speedup vs baseline: 1.0208x; 1.0208x over previous
#include <cuda_runtime.h>

// out[b,u] = prod_f(in[b,f]*w[f,u]) + bias[u] = P[b]*W[u] + bias[u]
// B=32768, F=32, U=256.
static constexpr int Bn = 32768;
static constexpr int Fn = 32;
static constexpr int Un = 256;

static constexpr int THREADS       = 256;          // 8 warps
static constexpr int ROWS_PER_WARP = 8;            // 2 independent LDG.128 / lane
static constexpr int ROWS_PER_BLK  = ROWS_PER_WARP * 8;   // 64
static constexpr int GRID          = Bn / ROWS_PER_BLK;   // 512 -> ONE wave

// Packed fp32x2 helpers (sm_103a FFMA2 is PTX-only).
__device__ __forceinline__ unsigned long long pk2(float lo, float hi) {
    unsigned long long r;
    asm("mov.b64 %0, {%1, %2};" : "=l"(r) : "f"(lo), "f"(hi));
    return r;
}
__device__ __forceinline__ unsigned long long fma2(unsigned long long a,
                                                   unsigned long long b,
                                                   unsigned long long c) {
    unsigned long long d;
    asm("fma.rn.f32x2 %0, %1, %2, %3;" : "=l"(d) : "l"(a), "l"(b), "l"(c));
    return d;
}

// One wave, everything resident, MLP=2 on the critical input load.
__global__ __launch_bounds__(THREADS)
void fused_kernel(const float* __restrict__ in,
                  const float* __restrict__ w,
                  const float* __restrict__ bias,
                  float* __restrict__ out) {
    __shared__ float sW[Un];

    const int t    = threadIdx.x;
    const int lane = t & 31;
    const int warp = t >> 5;

    // ---- issue BOTH input loads first: 8 rows * 32 f = 64 float4 ----
    // lane l: v0 covers rows 0..3 (float4 idx l), v1 rows 4..7 (idx l+32)
    const long long rowbase = (long long)blockIdx.x * ROWS_PER_BLK
                            + (long long)warp * ROWS_PER_WARP;
    const float4* in4 = reinterpret_cast<const float4*>(in + rowbase * Fn);
    const float4 v0 = in4[lane];
    const float4 v1 = in4[lane + 32];

    // ---- one-time W phase: thread t owns column t (L2-hit after wave start) ----
    {
        float q0 = 1.0f, q1 = 1.0f, q2 = 1.0f, q3 = 1.0f;
#pragma unroll
        for (int f = 0; f < Fn; f += 4) {
            q0 *= w[(f + 0) * Un + t];
            q1 *= w[(f + 1) * Un + t];
            q2 *= w[(f + 2) * Un + t];
            q3 *= w[(f + 3) * Un + t];
        }
        sW[t] = (q0 * q1) * (q2 * q3);
    }

    // bias -> regs, independent of everything above
    const float4* B4 = reinterpret_cast<const float4*>(bias);
    const float4 bv0 = B4[lane];
    const float4 bv1 = B4[lane + 32];

    __syncthreads();

    const float4* sW4 = reinterpret_cast<const float4*>(sW);
    const float4 wv0 = sW4[lane];
    const float4 wv1 = sW4[lane + 32];

    const unsigned long long w00 = pk2(wv0.x, wv0.y), w01 = pk2(wv0.z, wv0.w);
    const unsigned long long w10 = pk2(wv1.x, wv1.y), w11 = pk2(wv1.z, wv1.w);
    const unsigned long long b00 = pk2(bv0.x, bv0.y), b01 = pk2(bv0.z, bv0.w);
    const unsigned long long b10 = pk2(bv1.x, bv1.y), b11 = pk2(bv1.z, bv1.w);

    // ---- two interleaved row-product reductions (independent chains) ----
    float p0 = v0.x * v0.y * v0.z * v0.w;
    float p1 = v1.x * v1.y * v1.z * v1.w;
    p0 *= __shfl_xor_sync(0xffffffffu, p0, 1);
    p1 *= __shfl_xor_sync(0xffffffffu, p1, 1);
    p0 *= __shfl_xor_sync(0xffffffffu, p0, 2);
    p1 *= __shfl_xor_sync(0xffffffffu, p1, 2);
    p0 *= __shfl_xor_sync(0xffffffffu, p0, 4);
    p1 *= __shfl_xor_sync(0xffffffffu, p1, 4);
    // lanes 8r..8r+7: p0 = product of row (rowbase+r), p1 = row (rowbase+4+r)

    // ---- 16 coalesced STG.128 per warp, all independent ----
    ulonglong2* out2 = reinterpret_cast<ulonglong2*>(out + rowbase * Un);
#pragma unroll
    for (int r = 0; r < 4; ++r) {
        const float pr0 = __shfl_sync(0xffffffffu, p0, r * 8);
        const float pr1 = __shfl_sync(0xffffffffu, p1, r * 8);
        const unsigned long long pa = pk2(pr0, pr0);
        const unsigned long long pb = pk2(pr1, pr1);
        ulonglong2 oa0, oa1, ob0, ob1;
        oa0.x = fma2(pa, w00, b00);  oa0.y = fma2(pa, w01, b01);
        oa1.x = fma2(pa, w10, b10);  oa1.y = fma2(pa, w11, b11);
        ob0.x = fma2(pb, w00, b00);  ob0.y = fma2(pb, w01, b01);
        ob1.x = fma2(pb, w10, b10);  ob1.y = fma2(pb, w11, b11);
        // row stride = 256 floats = 64 ulonglong2
        out2[(r    ) * 64 + lane]      = oa0;   // row rowbase+r
        out2[(r    ) * 64 + lane + 32] = oa1;
        out2[(r + 4) * 64 + lane]      = ob0;   // row rowbase+4+r
        out2[(r + 4) * 64 + lane + 32] = ob1;
    }
}

extern "C" void kernel_launch(void* const* d_in, const int* in_sizes, int n_in,
                              void* d_out, int out_size) {
    // metadata order: inputs [B,F], weight [F,U], weight_selector [F,U] (dead), bias [U]
    const float* in   = (const float*)d_in[0];
    const float* w    = (const float*)d_in[1];
    const float* bias = (const float*)d_in[3];
    float* out        = (float*)d_out;

    fused_kernel<<<GRID, THREADS>>>(in, w, bias, out);
}

// round 14
// speedup vs baseline: 1.0239x; 1.0030x over previous
#include <cuda_runtime.h>

// out[b,u] = prod_f(in[b,f]*w[f,u]) + bias[u] = P[b]*W[u] + bias[u]
// B=32768, F=32, U=256.
static constexpr int Bn = 32768;
static constexpr int Fn = 32;
static constexpr int Un = 256;

static constexpr int THREADS       = 256;               // 8 warps
static constexpr int ROWS_PER_WARP = 8;                 // 2 independent LDG.128/lane
static constexpr int ROWS_PER_BLK  = ROWS_PER_WARP * 8; // 64
static constexpr int GRID          = Bn / ROWS_PER_BLK; // 512 -> one wave

// Packed fp32x2 helpers (sm_103a FFMA2 is PTX-only).
__device__ __forceinline__ unsigned long long pk2(float lo, float hi) {
    unsigned long long r;
    asm("mov.b64 %0, {%1, %2};" : "=l"(r) : "f"(lo), "f"(hi));
    return r;
}
__device__ __forceinline__ unsigned long long fma2(unsigned long long a,
                                                   unsigned long long b,
                                                   unsigned long long c) {
    unsigned long long d;
    asm("fma.rn.f32x2 %0, %1, %2, %3;" : "=l"(d) : "l"(a), "l"(b), "l"(c));
    return d;
}

__global__ __launch_bounds__(THREADS)
void fused_kernel(const float* __restrict__ in,
                  const float* __restrict__ w,
                  const float* __restrict__ bias,
                  float* __restrict__ out) {
    __shared__ float4 sW4[Un / 4];   // 64 float4 = 256 column products

    const int t    = threadIdx.x;
    const int lane = t & 31;
    const int warp = t >> 5;

    // ---- issue BOTH input loads first: 8 rows * 32 f = 64 float4 ----
    // lane l: v0 covers rows 0..3 (float4 idx l), v1 rows 4..7 (idx l+32)
    const long long rowbase = (long long)blockIdx.x * ROWS_PER_BLK
                            + (long long)warp * ROWS_PER_WARP;
    const float4* in4 = reinterpret_cast<const float4*>(in + rowbase * Fn);
    const float4 v0 = in4[lane];
    const float4 v1 = in4[lane + 32];

    // bias -> regs, independent of everything (L2 hit after wave start)
    const float4* B4 = reinterpret_cast<const float4*>(bias);
    const float4 bv0 = B4[lane];
    const float4 bv1 = B4[lane + 32];

    // ---- W phase: warps 0-1 only, vectorized float4 column products ----
    // warp 0 owns float4-columns 0..31, warp 1 owns 32..63.
    // 32 coalesced LDG.128 per warp (512B/warp/iter), two independent
    // accumulator chains for FMA-pipe ILP. Warps 2-7 skip to the barrier.
    if (warp < 2) {
        const float4* w4 = reinterpret_cast<const float4*>(w);
        const int c = lane + warp * 32;
        float4 qa = w4[c];              // f = 0
        float4 qb = w4[64 + c];         // f = 1
#pragma unroll
        for (int f = 2; f < Fn; f += 2) {
            const float4 a = w4[(f    ) * 64 + c];
            const float4 b = w4[(f + 1) * 64 + c];
            qa.x *= a.x; qa.y *= a.y; qa.z *= a.z; qa.w *= a.w;
            qb.x *= b.x; qb.y *= b.y; qb.z *= b.z; qb.w *= b.w;
        }
        float4 q;
        q.x = qa.x * qb.x; q.y = qa.y * qb.y;
        q.z = qa.z * qb.z; q.w = qa.w * qb.w;
        sW4[c] = q;
    }

    __syncthreads();

    const float4 wv0 = sW4[lane];
    const float4 wv1 = sW4[lane + 32];

    const unsigned long long w00 = pk2(wv0.x, wv0.y), w01 = pk2(wv0.z, wv0.w);
    const unsigned long long w10 = pk2(wv1.x, wv1.y), w11 = pk2(wv1.z, wv1.w);
    const unsigned long long b00 = pk2(bv0.x, bv0.y), b01 = pk2(bv0.z, bv0.w);
    const unsigned long long b10 = pk2(bv1.x, bv1.y), b11 = pk2(bv1.z, bv1.w);

    // ---- two interleaved row-product reductions (independent chains) ----
    float p0 = v0.x * v0.y * v0.z * v0.w;
    float p1 = v1.x * v1.y * v1.z * v1.w;
    p0 *= __shfl_xor_sync(0xffffffffu, p0, 1);
    p1 *= __shfl_xor_sync(0xffffffffu, p1, 1);
    p0 *= __shfl_xor_sync(0xffffffffu, p0, 2);
    p1 *= __shfl_xor_sync(0xffffffffu, p1, 2);
    p0 *= __shfl_xor_sync(0xffffffffu, p0, 4);
    p1 *= __shfl_xor_sync(0xffffffffu, p1, 4);
    // lanes 8r..8r+7: p0 = product of row (rowbase+r), p1 = row (rowbase+4+r)

    // ---- 16 coalesced STG.128 per warp, all independent ----
    ulonglong2* out2 = reinterpret_cast<ulonglong2*>(out + rowbase * Un);
#pragma unroll
    for (int r = 0; r < 4; ++r) {
        const float pr0 = __shfl_sync(0xffffffffu, p0, r * 8);
        const float pr1 = __shfl_sync(0xffffffffu, p1, r * 8);
        const unsigned long long pa = pk2(pr0, pr0);
        const unsigned long long pb = pk2(pr1, pr1);
        ulonglong2 oa0, oa1, ob0, ob1;
        oa0.x = fma2(pa, w00, b00);  oa0.y = fma2(pa, w01, b01);
        oa1.x = fma2(pa, w10, b10);  oa1.y = fma2(pa, w11, b11);
        ob0.x = fma2(pb, w00, b00);  ob0.y = fma2(pb, w01, b01);
        ob1.x = fma2(pb, w10, b10);  ob1.y = fma2(pb, w11, b11);
        // row stride = 256 floats = 64 ulonglong2
        out2[(r    ) * 64 + lane]      = oa0;   // row rowbase+r
        out2[(r    ) * 64 + lane + 32] = oa1;
        out2[(r + 4) * 64 + lane]      = ob0;   // row rowbase+4+r
        out2[(r + 4) * 64 + lane + 32] = ob1;
    }
}

extern "C" void kernel_launch(void* const* d_in, const int* in_sizes, int n_in,
                              void* d_out, int out_size) {
    // metadata order: inputs [B,F], weight [F,U], weight_selector [F,U] (dead), bias [U]
    const float* in   = (const float*)d_in[0];
    const float* w    = (const float*)d_in[1];
    const float* bias = (const float*)d_in[3];
    float* out        = (float*)d_out;

    fused_kernel<<<GRID, THREADS>>>(in, w, bias, out);
}